// round 5
// baseline (speedup 1.0000x reference)
#include <cuda_runtime.h>

#define NSAMP  2048            // 32 * 64
#define IMG    512
#define NCHAN  3
#define NTERMS (NSAMP * NCHAN) // 6144
#define LPT    4               // lanes per term
#define TPB    128
#define NBLOCKS ((NTERMS * LPT) / TPB)   // 192
#define NWARPS (NBLOCKS * (TPB / 32))    // 768

__device__ float        g_acc;   // zero at load; last warp resets each run
__device__ unsigned int g_cnt;

__device__ __forceinline__ int reflect_idx(int t) {
    t = (t < 0) ? -t : t;
    t = (t >= IMG) ? (2 * IMG - 2 - t) : t;
    return t;
}

// horizontal 7-tap at shift0/shift1 from a 12-float aligned cover, select by sh
__device__ __forceinline__ void hconv12(const float* __restrict__ f, int sh,
                                        const float* __restrict__ kk,
                                        float& h0, float& hsh) {
    float H[5];
    #pragma unroll
    for (int m = 0; m < 5; m++) {
        float acc = 0.0f;
        #pragma unroll
        for (int j = 0; j < 7; j++) acc += kk[j] * f[m + j];
        H[m] = acc;
    }
    h0  = (sh == 0) ? H[0] : (sh == 1) ? H[1] : (sh == 2) ? H[2] : H[3];
    hsh = (sh == 0) ? H[1] : (sh == 1) ? H[2] : (sh == 2) ? H[3] : H[4];
}

__global__ __launch_bounds__(TPB)
void color_loss_kernel(const float* __restrict__ pred,   // [32,64,8]
                       const float* __restrict__ img,    // [32,3,512,512]
                       float* __restrict__ out)
{
    const float kk[7] = {
        0.0044330481752437470f, 0.0540055826225118500f, 0.2420362293759061000f,
        0.3990502796524549000f,
        0.2420362293759061000f, 0.0540055826225118500f, 0.0044330481752437470f
    };

    const int gid  = blockIdx.x * TPB + threadIdx.x;
    const int term = gid >> 2;        // 0..6143 (grid exact)
    const int sub  = gid & 3;         // handles window rows 2*sub, 2*sub+1

    const int s = term / NCHAN;
    const int c = term - s * NCHAN;
    const int b = s >> 6;

    const float* p = pred + (size_t)s * 8;
    const float4 pa = *(const float4*)p;
    const float4 pb = *(const float4*)(p + 4);
    const float px  = pa.x;
    const float py  = pa.y;
    const float col = (c == 0) ? pb.y : (c == 1) ? pb.z : pb.w;

    // exact reference arithmetic chain
    const float gx = 2.0f * px - 1.0f;
    const float gy = 2.0f * py - 1.0f;
    float x = ((gx + 1.0f) * (float)IMG - 1.0f) * 0.5f;
    float y = ((gy + 1.0f) * (float)IMG - 1.0f) * 0.5f;
    x = fminf(fmaxf(x, 0.0f), (float)(IMG - 1));
    y = fminf(fmaxf(y, 0.0f), (float)(IMG - 1));

    const float x0f = floorf(x);
    const float y0f = floorf(y);
    const float wx = x - x0f;
    const float wy = y - y0f;
    const int x0 = (int)x0f;
    const int y0 = (int)y0f;
    const bool xs = (x0 + 1 <= IMG - 1);
    const bool ys = (y0 + 1 <= IMG - 1);

    const float* base = img + ((size_t)b * NCHAN + c) * (size_t)(IMG * IMG);

    const int r0 = 2 * sub;
    const int r1 = 2 * sub + 1;
    const int ry0 = reflect_idx(y0 - 3 + r0);
    const int ry1 = reflect_idx(y0 - 3 + r1);
    const float* rp0 = base + (size_t)ry0 * IMG;
    const float* rp1 = base + (size_t)ry1 * IMG;

    const int xbase = x0 - 3;
    const int a = xbase & ~3;

    float h0a, h1a, h0b, h1b;
    if (xbase >= 0 && a + 12 <= IMG) {
        const int sh = xbase - a;     // 0..3
        // batch all 6 independent LDG.128 up front (max MLP)
        const float4 a0 = *(const float4*)(rp0 + a);
        const float4 a1 = *(const float4*)(rp0 + a + 4);
        const float4 a2 = *(const float4*)(rp0 + a + 8);
        const float4 b0 = *(const float4*)(rp1 + a);
        const float4 b1 = *(const float4*)(rp1 + a + 4);
        const float4 b2 = *(const float4*)(rp1 + a + 8);
        const float fa[12] = { a0.x,a0.y,a0.z,a0.w, a1.x,a1.y,a1.z,a1.w, a2.x,a2.y,a2.z,a2.w };
        const float fb[12] = { b0.x,b0.y,b0.z,b0.w, b1.x,b1.y,b1.z,b1.w, b2.x,b2.y,b2.z,b2.w };
        hconv12(fa, sh, kk, h0a, h1a);
        hconv12(fb, sh, kk, h0b, h1b);
    } else {
        float pv0[8], pv1[8];
        #pragma unroll
        for (int j = 0; j < 8; j++) {
            const int cxj = reflect_idx(xbase + j);
            pv0[j] = __ldg(&rp0[cxj]);
            pv1[j] = __ldg(&rp1[cxj]);
        }
        h0a = 0.0f; h1a = 0.0f; h0b = 0.0f; h1b = 0.0f;
        #pragma unroll
        for (int j = 0; j < 7; j++) {
            h0a += kk[j] * pv0[j];
            h1a += kk[j] * pv0[j + 1];
            h0b += kk[j] * pv1[j];
            h1b += kk[j] * pv1[j + 1];
        }
    }
    if (!xs) { h1a = h0a; h1b = h0b; }

    // fuse bilinear-in-x and vertical kernel weights => one scalar per lane
    const float hxa = h0a * (1.0f - wx) + h1a * wx;
    const float hxb = h0b * (1.0f - wx) + h1b * wx;

    const float wv0_a = (r0 < 7) ? kk[r0] : 0.0f;
    const float wv1_a = (r0 > 0) ? kk[r0 - 1] : 0.0f;
    const float wv0b  = (r1 < 7) ? kk[r1] : 0.0f;
    const float wv1_b = kk[r1 - 1];

    const float wsel_a = ys ? wv1_a : wv0_a;
    const float wsel_b = ys ? wv1_b : wv0b;

    float contrib = hxa * (wv0_a * (1.0f - wy) + wsel_a * wy)
                  + hxb * (wv0b  * (1.0f - wy) + wsel_b * wy);

    // reduce 4 lanes of this term (4-aligned lane groups)
    contrib += __shfl_xor_sync(0xffffffffu, contrib, 1);
    contrib += __shfl_xor_sync(0xffffffffu, contrib, 2);

    float local = 0.0f;
    if (sub == 0) {
        const float d = col - contrib;    // contrib == target
        local = d * d * (1.0f / (float)NTERMS);
    }

    // warp reduce (5 shfls)
    #pragma unroll
    for (int o = 16; o > 0; o >>= 1)
        local += __shfl_down_sync(0xffffffffu, local, o);

    // per-warp finalize: no smem/bar tail, warps fire independently
    if ((threadIdx.x & 31) == 0) {
        atomicAdd(&g_acc, local);
        __threadfence();
        const unsigned int done = atomicAdd(&g_cnt, 1u);
        if (done == (unsigned int)(NWARPS - 1)) {
            // last warp: all g_acc adds are ordered before their g_cnt bumps
            const float total = atomicAdd(&g_acc, 0.0f);
            out[0] = total;
            g_acc = 0.0f;
            g_cnt = 0u;
            __threadfence();
        }
    }
}

extern "C" void kernel_launch(void* const* d_in, const int* in_sizes, int n_in,
                              void* d_out, int out_size) {
    const float* pred = (const float*)d_in[0];
    const float* img  = (const float*)d_in[1];
    if (n_in >= 2 && in_sizes[0] != NSAMP * 8) {
        pred = (const float*)d_in[1];
        img  = (const float*)d_in[0];
    }
    float* out = (float*)d_out;

    color_loss_kernel<<<NBLOCKS, TPB>>>(pred, img, out);
}

// round 6
// speedup vs baseline: 1.1481x; 1.1481x over previous
#include <cuda_runtime.h>

#define NSAMP  2048            // 32 * 64
#define IMG    512
#define NCHAN  3
#define NTERMS (NSAMP * NCHAN) // 6144
#define TPB    256
#define NBLOCKS ((NTERMS * 4) / TPB)   // 96

__device__ float        g_acc;   // zero at load; last block resets each run
__device__ unsigned int g_cnt;

__device__ __forceinline__ int reflect_idx(int t) {
    t = (t < 0) ? -t : t;
    t = (t >= IMG) ? (2 * IMG - 2 - t) : t;
    return t;
}

// horizontal 7-tap at shift0/shift1 from a 12-float aligned cover, select by sh
__device__ __forceinline__ void hconv12(const float* __restrict__ f, int sh,
                                        const float* __restrict__ kk,
                                        float& h0, float& hsh) {
    float H[5];
    #pragma unroll
    for (int m = 0; m < 5; m++) {
        float acc = 0.0f;
        #pragma unroll
        for (int j = 0; j < 7; j++) acc += kk[j] * f[m + j];
        H[m] = acc;
    }
    h0  = (sh == 0) ? H[0] : (sh == 1) ? H[1] : (sh == 2) ? H[2] : H[3];
    hsh = (sh == 0) ? H[1] : (sh == 1) ? H[2] : (sh == 2) ? H[3] : H[4];
}

__global__ __launch_bounds__(TPB)
void color_loss_kernel(const float* __restrict__ pred,   // [32,64,8]
                       const float* __restrict__ img,    // [32,3,512,512]
                       float* __restrict__ out)
{
    const float kk[7] = {
        0.0044330481752437470f, 0.0540055826225118500f, 0.2420362293759061000f,
        0.3990502796524549000f,
        0.2420362293759061000f, 0.0540055826225118500f, 0.0044330481752437470f
    };

    const int gid  = blockIdx.x * TPB + threadIdx.x;
    const int term = gid >> 2;        // 0..6143 (grid exact)
    const int sub  = gid & 3;         // handles window rows 2*sub, 2*sub+1

    const int s = term / NCHAN;
    const int c = term - s * NCHAN;
    const int b = s >> 6;

    const float* p = pred + (size_t)s * 8;
    const float4 pa = *(const float4*)p;
    const float4 pb = *(const float4*)(p + 4);
    const float px  = pa.x;
    const float py  = pa.y;
    const float col = (c == 0) ? pb.y : (c == 1) ? pb.z : pb.w;

    // exact reference arithmetic chain
    const float gx = 2.0f * px - 1.0f;
    const float gy = 2.0f * py - 1.0f;
    float x = ((gx + 1.0f) * (float)IMG - 1.0f) * 0.5f;
    float y = ((gy + 1.0f) * (float)IMG - 1.0f) * 0.5f;
    x = fminf(fmaxf(x, 0.0f), (float)(IMG - 1));
    y = fminf(fmaxf(y, 0.0f), (float)(IMG - 1));

    const float x0f = floorf(x);
    const float y0f = floorf(y);
    const float wx = x - x0f;
    const float wy = y - y0f;
    const int x0 = (int)x0f;
    const int y0 = (int)y0f;
    const bool xs = (x0 + 1 <= IMG - 1);
    const bool ys = (y0 + 1 <= IMG - 1);

    const float* base = img + ((size_t)b * NCHAN + c) * (size_t)(IMG * IMG);

    const int r0 = 2 * sub;
    const int r1 = 2 * sub + 1;
    const int ry0 = reflect_idx(y0 - 3 + r0);
    const int ry1 = reflect_idx(y0 - 3 + r1);
    const float* rp0 = base + (size_t)ry0 * IMG;
    const float* rp1 = base + (size_t)ry1 * IMG;

    const int xbase = x0 - 3;
    const int a = xbase & ~3;

    float h0a, h1a, h0b, h1b;
    if (xbase >= 0 && a + 12 <= IMG) {
        const int sh = xbase - a;     // 0..3
        // batch all 6 independent LDG.128 up front (max MLP)
        const float4 a0 = *(const float4*)(rp0 + a);
        const float4 a1 = *(const float4*)(rp0 + a + 4);
        const float4 a2 = *(const float4*)(rp0 + a + 8);
        const float4 b0 = *(const float4*)(rp1 + a);
        const float4 b1 = *(const float4*)(rp1 + a + 4);
        const float4 b2 = *(const float4*)(rp1 + a + 8);
        const float fa[12] = { a0.x,a0.y,a0.z,a0.w, a1.x,a1.y,a1.z,a1.w, a2.x,a2.y,a2.z,a2.w };
        const float fb[12] = { b0.x,b0.y,b0.z,b0.w, b1.x,b1.y,b1.z,b1.w, b2.x,b2.y,b2.z,b2.w };
        hconv12(fa, sh, kk, h0a, h1a);
        hconv12(fb, sh, kk, h0b, h1b);
    } else {
        float pv0[8], pv1[8];
        #pragma unroll
        for (int j = 0; j < 8; j++) {
            const int cxj = reflect_idx(xbase + j);
            pv0[j] = __ldg(&rp0[cxj]);
            pv1[j] = __ldg(&rp1[cxj]);
        }
        h0a = 0.0f; h1a = 0.0f; h0b = 0.0f; h1b = 0.0f;
        #pragma unroll
        for (int j = 0; j < 7; j++) {
            h0a += kk[j] * pv0[j];
            h1a += kk[j] * pv0[j + 1];
            h0b += kk[j] * pv1[j];
            h1b += kk[j] * pv1[j + 1];
        }
    }
    if (!xs) { h1a = h0a; h1b = h0b; }

    // fuse bilinear-in-x and vertical kernel weights => one scalar per lane
    const float hxa = h0a * (1.0f - wx) + h1a * wx;
    const float hxb = h0b * (1.0f - wx) + h1b * wx;

    const float wv0_a = (r0 < 7) ? kk[r0] : 0.0f;
    const float wv1_a = (r0 > 0) ? kk[r0 - 1] : 0.0f;
    const float wv0b  = (r1 < 7) ? kk[r1] : 0.0f;
    const float wv1_b = kk[r1 - 1];

    const float wsel_a = ys ? wv1_a : wv0_a;
    const float wsel_b = ys ? wv1_b : wv0b;

    float contrib = hxa * (wv0_a * (1.0f - wy) + wsel_a * wy)
                  + hxb * (wv0b  * (1.0f - wy) + wsel_b * wy);

    // reduce 4 lanes of this term (4-aligned lane groups)
    contrib += __shfl_xor_sync(0xffffffffu, contrib, 1);
    contrib += __shfl_xor_sync(0xffffffffu, contrib, 2);

    float local = 0.0f;
    if (sub == 0) {
        const float d = col - contrib;    // contrib == target
        local = d * d * (1.0f / (float)NTERMS);
    }

    // warp reduce (5 shfls)
    #pragma unroll
    for (int o = 16; o > 0; o >>= 1)
        local += __shfl_down_sync(0xffffffffu, local, o);

    __shared__ float ws[TPB / 32];
    const int lane = threadIdx.x & 31;
    const int wid  = threadIdx.x >> 5;
    if (lane == 0) ws[wid] = local;
    __syncthreads();

    // block-level finalize: one atomic pair per block (96 total — cheap)
    if (threadIdx.x == 0) {
        float bsum = 0.0f;
        #pragma unroll
        for (int w = 0; w < TPB / 32; w++) bsum += ws[w];

        atomicAdd(&g_acc, bsum);
        __threadfence();
        const unsigned int done = atomicAdd(&g_cnt, 1u);
        if (done == (unsigned int)(NBLOCKS - 1)) {
            const float total = atomicAdd(&g_acc, 0.0f);
            out[0] = total;
            g_acc = 0.0f;
            g_cnt = 0u;
            __threadfence();
        }
    }
}

extern "C" void kernel_launch(void* const* d_in, const int* in_sizes, int n_in,
                              void* d_out, int out_size) {
    const float* pred = (const float*)d_in[0];
    const float* img  = (const float*)d_in[1];
    if (n_in >= 2 && in_sizes[0] != NSAMP * 8) {
        pred = (const float*)d_in[1];
        img  = (const float*)d_in[0];
    }
    float* out = (float*)d_out;

    color_loss_kernel<<<NBLOCKS, TPB>>>(pred, img, out);
}